// round 1
// baseline (speedup 1.0000x reference)
#include <cuda_runtime.h>

#define D_ 256
#define BATCH 1024
#define TOLF 1e-4f
// float32(pi), matching jnp.pi cast to f32
#define PI_F 3.14159274101257324f
// sigmoid(±18) is within 1.5e-8 of {1,0}; 18/256 rad classification margin
#define DELTA 0.0703125f

struct __align__(16) Params {
    float cx, cy, dirx, diry;
    float ap, g_hi, g_lo, yn;
};

__device__ Params g_params[BATCH];

// One thread per batch: replicate reference per-batch math exactly.
__global__ void precompute_kernel(const float* __restrict__ x) {
    int b = blockIdx.x * blockDim.x + threadIdx.x;
    if (b >= BATCH) return;
    const float* xb = x + b * 5;
    float x0 = xb[0], x1 = xb[1], x2 = xb[2], x3 = xb[3], x4 = xb[4];
    Params p;
    p.cx = 256.0f * x0;
    p.cy = 256.0f * x1;
    float vv = x2 * x2 + x3 * x3;
    float rv = rsqrtf(fmaxf(vv, 1e-12f));      // l2_normalize w/ eps, as reference
    p.dirx = x2 * rv;
    p.diry = x3 * rv;
    p.yn = sqrtf(p.dirx * p.dirx + p.diry * p.diry);
    p.ap = PI_F * x4;
    // Saturation thresholds in cos-space. cos is decreasing on [0,pi]:
    //   angle <= ap - DELTA  <=>  g >= cos(ap - DELTA)   -> sigmoid ~= 1
    //   angle >= ap + DELTA  <=>  g <= cos(ap + DELTA)   -> sigmoid ~= 0
    float th = p.ap - DELTA;
    p.g_hi = (th > 0.0f) ? cosf(th) : 2.0f;    // 2.0 = unreachable (g <= 1+eps)
    float tl = p.ap + DELTA;
    p.g_lo = (tl < PI_F) ? cosf(tl) : -2.0f;   // -2.0 = unreachable
    g_params[b] = p;
}

// Exact fp32 replication of the reference branchless-masked Heron formula.
__device__ __noinline__ float slow_pixel(float iu, float ju, float uu, Params p) {
    float r = rsqrtf(fmaxf(uu, 1e-12f));
    float nux = iu * r, nuy = ju * r;
    float dxx = nux - p.dirx, dyy = nuy - p.diry;
    float c  = sqrtf(dxx * dxx + dyy * dyy);
    float xn = sqrtf(nux * nux + nuy * nuy);
    bool ctp = c > (2.0f - TOLF);
    bool oor = (c < TOLF) || ctp || (xn < TOLF);
    float cs  = oor ? 1.0f : c;
    float xns = oor ? 1.0f : xn;
    float yns = oor ? 1.0f : p.yn;
    float a   = fmaxf(xns, yns);
    float bb  = fminf(xns, yns);
    float mbc = fmaxf(bb, cs);
    float nbc = fminf(bb, cs);
    float mu  = nbc - (a - mbc);
    float num = (a - bb + cs) * mu;
    float den = (a + (bb + cs)) * (a - cs + bb);
    float angle = 2.0f * atanf(sqrtf(num / den));
    angle = (oor ? 0.0f : angle) + (ctp ? PI_F : 0.0f);
    float t = 256.0f * (p.ap - angle);
    return 1.0f / (1.0f + expf(-t));     // t in [-805, 805]; expf(inf)->0 output, ok
}

// Grid: (BATCH, 4). Block: 256 threads (8 warps). Each block covers 64 rows
// of one batch image; a warp stores 32 consecutive columns (128B coalesced).
__global__ void __launch_bounds__(256) cones_kernel(float* __restrict__ out) {
    const int b = blockIdx.x;
    const Params p = g_params[b];
    const int lane = threadIdx.x & 31;
    const int warp = threadIdx.x >> 5;
    const int rowBase = blockIdx.y * 64;
    float* outB = out + (size_t)b * (D_ * D_);

    #pragma unroll 1
    for (int jseg = 0; jseg < 8; jseg++) {
        const int j = jseg * 32 + lane;
        const float ju  = (float)j - p.cy;
        const float ju2 = ju * ju;
        const float jd  = ju * p.diry;
        #pragma unroll 1
        for (int ii = 0; ii < 8; ii++) {
            const int i = rowBase + ii * 8 + warp;
            const float iu  = (float)i - p.cx;
            const float uu  = fmaf(iu, iu, ju2);
            const float dot = fmaf(iu, p.dirx, jd);
            const float g   = dot * rsqrtf(uu);

            // Saturated fast paths; everything ambiguous/degenerate -> slow.
            float val = (g >= p.g_hi) ? 1.0f : 0.0f;
            bool needSlow = ((g > p.g_lo) && (g < p.g_hi)) || !(uu >= 1e-12f);
            if (needSlow) {
                val = slow_pixel(iu, ju, uu, p);
            }
            outB[i * D_ + j] = val;
        }
    }
}

extern "C" void kernel_launch(void* const* d_in, const int* in_sizes, int n_in,
                              void* d_out, int out_size) {
    const float* x = (const float*)d_in[0];   // [1024, 5] f32
    // d_in[1] = coordinates is a deterministic meshgrid (i, j); derived from
    // indices in-kernel instead of loading it.
    float* out = (float*)d_out;               // [1024, 256, 256, 1] f32

    precompute_kernel<<<4, 256>>>(x);
    dim3 grid(BATCH, 4);
    cones_kernel<<<grid, 256>>>(out);
}